// round 14
// baseline (speedup 1.0000x reference)
#include <cuda_runtime.h>
#include <cstdint>

#define NROWS 8192
#define DDIM  512
#define BM    128                      /* tile rows  */
#define BN    64                       /* tile cols  */
#define BK    64                       /* K per stage */
#define NITER (DDIM/BK)                /* 8 */
#define NT2   4160                     /* tiles: sum_{I=0}^{63}(128-2I) */
#define STRB  80                       /* smem row stride bytes */
#define TILEB2 ((BM+BN)*STRB)          /* 15360 B per stage (A 128 rows + B 64) */
#define STAGES 4
#define SMEM_DYN (STAGES*TILEB2)       /* 61440 B */
#define LMARGIN 0.5f
#define FBIG  3.402823466e+38f

// ---------------- scratch (static device globals; no allocation) -------------
__device__ int8_t   g_q8[NROWS*DDIM];
__device__ float    g_scl[NROWS];
__device__ unsigned g_minpos[NROWS];
__device__ unsigned g_maxneg[NROWS];
__device__ int      g_tgt[NROWS];
__device__ unsigned g_done;

__device__ __forceinline__ unsigned ordu(float f) {
    unsigned u = __float_as_uint(f);
    return (u & 0x80000000u) ? ~u : (u | 0x80000000u);
}
__device__ __forceinline__ float deordu(unsigned u) {
    return (u & 0x80000000u) ? __uint_as_float(u & 0x7fffffffu)
                             : __uint_as_float(~u);
}
__device__ __forceinline__ uint32_t smem_u32(const void* p) {
    uint32_t a;
    asm("{ .reg .u64 t; cvta.to.shared.u64 t, %1; cvt.u32.u64 %0, t; }"
        : "=r"(a) : "l"(p));
    return a;
}
__device__ __forceinline__ void cpasync16(uint32_t dst, const void* src) {
    asm volatile("cp.async.cg.shared.global [%0], [%1], 16;"
                 :: "r"(dst), "l"(src) : "memory");
}
__device__ __forceinline__ void cpcommit() {
    asm volatile("cp.async.commit_group;" ::: "memory");
}
template <int N>
__device__ __forceinline__ void cpwait() {
    asm volatile("cp.async.wait_group %0;" :: "n"(N) : "memory");
}
__device__ __forceinline__ void ldsm4(unsigned* r, uint32_t addr) {
    asm volatile("ldmatrix.sync.aligned.m8n8.x4.shared.b16 {%0,%1,%2,%3}, [%4];"
                 : "=r"(r[0]), "=r"(r[1]), "=r"(r[2]), "=r"(r[3]) : "r"(addr));
}
__device__ __forceinline__ void mma_s8(int* c, const unsigned* a, const unsigned* b)
{
    asm volatile(
        "mma.sync.aligned.m16n8k32.row.col.s32.s8.s8.s32 "
        "{%0,%1,%2,%3},{%4,%5,%6,%7},{%8,%9},{%0,%1,%2,%3};"
        : "+r"(c[0]), "+r"(c[1]), "+r"(c[2]), "+r"(c[3])
        : "r"(a[0]), "r"(a[1]), "r"(a[2]), "r"(a[3]), "r"(b[0]), "r"(b[1]));
}

// -------- kernel 1: L2-normalize -> int8 quant (2 rows per warp) + resets ----
__global__ void k_normalize(const float* __restrict__ x, const int* __restrict__ t32)
{
    int tid  = threadIdx.x;
    int wid  = tid >> 5;
    int lane = tid & 31;
    int r0   = blockIdx.x * 16 + wid * 2;
    int r1   = r0 + 1;

    if (blockIdx.x == 0 && tid == 0) g_done = 0;

    const float4* x0 = (const float4*)(x + (size_t)r0 * DDIM);
    const float4* x1 = (const float4*)(x + (size_t)r1 * DDIM);
    float4 v0[4], v1[4];
    #pragma unroll
    for (int i = 0; i < 4; i++) { v0[i] = x0[lane + 32*i]; v1[i] = x1[lane + 32*i]; }

    float ss0 = 0.f, ma0 = 0.f, ss1 = 0.f, ma1 = 0.f;
    #pragma unroll
    for (int i = 0; i < 4; i++) {
        ss0 += v0[i].x*v0[i].x + v0[i].y*v0[i].y + v0[i].z*v0[i].z + v0[i].w*v0[i].w;
        ma0  = fmaxf(ma0, fmaxf(fmaxf(fabsf(v0[i].x), fabsf(v0[i].y)),
                                fmaxf(fabsf(v0[i].z), fabsf(v0[i].w))));
        ss1 += v1[i].x*v1[i].x + v1[i].y*v1[i].y + v1[i].z*v1[i].z + v1[i].w*v1[i].w;
        ma1  = fmaxf(ma1, fmaxf(fmaxf(fabsf(v1[i].x), fabsf(v1[i].y)),
                                fmaxf(fabsf(v1[i].z), fabsf(v1[i].w))));
    }
    #pragma unroll
    for (int o = 16; o > 0; o >>= 1) {
        ss0 += __shfl_xor_sync(0xffffffffu, ss0, o);
        ma0  = fmaxf(ma0, __shfl_xor_sync(0xffffffffu, ma0, o));
        ss1 += __shfl_xor_sync(0xffffffffu, ss1, o);
        ma1  = fmaxf(ma1, __shfl_xor_sync(0xffffffffu, ma1, o));
    }
    float qs0 = 127.0f / ma0, scl0 = ma0 * rsqrtf(ss0) * (1.0f/127.0f);
    float qs1 = 127.0f / ma1, scl1 = ma1 * rsqrtf(ss1) * (1.0f/127.0f);

    int hv = t32[2*lane + 1];
    unsigned bal = __ballot_sync(0xffffffffu, hv == 0);
    bool is64 = (bal == 0xffffffffu);
    if (lane < 2) {
        int   row = lane ? r1 : r0;
        float scl = lane ? scl1 : scl0;
        g_minpos[row] = ordu(FBIG);
        g_maxneg[row] = ordu(-FBIG);
        g_tgt[row]    = is64 ? t32[2*row] : t32[row];
        g_scl[row]    = scl;
    }

    #pragma unroll
    for (int i = 0; i < 4; i++) {
        int a0 = __float2int_rn(v0[i].x*qs0), a1 = __float2int_rn(v0[i].y*qs0);
        int a2 = __float2int_rn(v0[i].z*qs0), a3 = __float2int_rn(v0[i].w*qs0);
        unsigned p0 = (unsigned)(a0 & 0xff) | ((unsigned)(a1 & 0xff) << 8) |
                      ((unsigned)(a2 & 0xff) << 16) | ((unsigned)(a3 & 0xff) << 24);
        *(unsigned*)(g_q8 + (size_t)r0 * DDIM + (lane + 32*i)*4) = p0;
        int b0 = __float2int_rn(v1[i].x*qs1), b1 = __float2int_rn(v1[i].y*qs1);
        int b2 = __float2int_rn(v1[i].z*qs1), b3 = __float2int_rn(v1[i].w*qs1);
        unsigned p1 = (unsigned)(b0 & 0xff) | ((unsigned)(b1 & 0xff) << 8) |
                      ((unsigned)(b2 & 0xff) << 16) | ((unsigned)(b3 & 0xff) << 24);
        *(unsigned*)(g_q8 + (size_t)r1 * DDIM + (lane + 32*i)*4) = p1;
    }
}

// ------- kernel 2: 128x64-tile int8 GEMM + min/max + fused final -------------
// Tiles {(I,J): 0<=I<64, 2I<=J<128} cover the upper triangle (overlap near the
// diagonal is harmless: min/max are idempotent, S and the mask are symmetric).
// 256 threads = 8 warps (4 row-strips x 2 col-strips), 32x32 per warp.
// acc = 32 regs => 3 CTAs/SM (6 warps/SMSP) for latency hiding.
__global__ void __launch_bounds__(256, 3) k_gemm_reduce(float* __restrict__ out)
{
    extern __shared__ __align__(16) char dsm[];

    // decode tile: I row-block (128), J col-block (64), J >= 2I
    int b = blockIdx.x;
    int I = 0;
    while (b >= 128 - 2*I) { b -= 128 - 2*I; I++; }
    int J = 2*I + b;
    int rowBase = I * BM;
    int colBase = J * BN;

    __shared__ int   sTi[BM], sTj[BN];
    __shared__ float sSa[BM], sSb[BN];
    __shared__ int   sLast;

    int tid  = threadIdx.x;
    int wid  = tid >> 5;
    int lane = tid & 31;
    int wr   = wid >> 1;          // 0..3 : rows wr*32..+31
    int wc   = wid & 1;           // 0..1 : cols wc*32..+31
    int g    = lane >> 2;         // 0..7
    int t4   = lane & 3;          // 0..3

    if (tid < BM) {
        sTi[tid] = g_tgt[rowBase + tid];
        sSa[tid] = g_scl[rowBase + tid];
    } else if (tid < BM + BN) {   // FIX: only BN threads load column metadata
        int c2 = tid - BM;
        sTj[c2] = g_tgt[colBase + c2];
        sSb[c2] = g_scl[colBase + c2];
    }

    uint32_t dsmBase = smem_u32(dsm);

    // cp.async: A = 512 16B-chunks (2/thread), B = 256 chunks (1/thread)
    const int8_t *pA0, *pA1, *pB0;
    unsigned smA0, smA1, smB0;
    {
        int i0 = tid,       r0 = i0 >> 2, s0 = i0 & 3;
        int i1 = 256 + tid, r1 = i1 >> 2, s1 = i1 & 3;
        int rB = tid >> 2,  sB = tid & 3;
        pA0 = g_q8 + (size_t)(rowBase + r0)*DDIM + s0*16;
        pA1 = g_q8 + (size_t)(rowBase + r1)*DDIM + s1*16;
        pB0 = g_q8 + (size_t)(colBase + rB)*DDIM + sB*16;
        smA0 = r0*STRB + s0*16;
        smA1 = r1*STRB + s1*16;
        smB0 = BM*STRB + rB*STRB + sB*16;
    }
    auto issue_stage = [&](int s) {
        uint32_t d = dsmBase + (unsigned)(s & (STAGES-1)) * TILEB2;
        cpasync16(d + smA0, pA0); pA0 += BK;
        cpasync16(d + smA1, pA1); pA1 += BK;
        cpasync16(d + smB0, pB0); pB0 += BK;
        cpcommit();
    };

    unsigned aoff[2], boff[2];
    {
        int rsel = lane & 15;
        int kby  = ((lane >> 4) & 1) * 16;
        #pragma unroll
        for (int mt = 0; mt < 2; mt++)
            aoff[mt] = (wr*32 + mt*16 + rsel)*STRB + kby;
        #pragma unroll
        for (int np = 0; np < 2; np++)
            boff[np] = BM*STRB + (wc*32 + np*16 + rsel)*STRB + kby;
    }

    int acc[2][4][4];
    #pragma unroll
    for (int mt = 0; mt < 2; mt++)
        #pragma unroll
        for (int nt = 0; nt < 4; nt++)
            #pragma unroll
            for (int e = 0; e < 4; e++) acc[mt][nt][e] = 0;

    issue_stage(0);
    issue_stage(1);
    issue_stage(2);

    #pragma unroll
    for (int c = 0; c < NITER; c++) {
        cpwait<2>();
        __syncthreads();
        if (c + 3 < NITER) issue_stage(c + 3);
        else cpcommit();

        uint32_t bS = dsmBase + (unsigned)(c & (STAGES-1)) * TILEB2;
        #pragma unroll
        for (int ks = 0; ks < 2; ks++) {
            unsigned kk = ks*32;
            unsigned afr[2][4], btmp[2][4];
            #pragma unroll
            for (int mt = 0; mt < 2; mt++) ldsm4(afr[mt], bS + aoff[mt] + kk);
            #pragma unroll
            for (int np = 0; np < 2; np++) ldsm4(btmp[np], bS + boff[np] + kk);
            #pragma unroll
            for (int mt = 0; mt < 2; mt++) {
                #pragma unroll
                for (int np = 0; np < 2; np++) {
                    unsigned b0[2] = { btmp[np][0], btmp[np][2] };
                    unsigned b1[2] = { btmp[np][1], btmp[np][3] };
                    mma_s8(acc[mt][2*np],   afr[mt], b0);
                    mma_s8(acc[mt][2*np+1], afr[mt], b1);
                }
            }
        }
    }
    __syncthreads();   // compute done; overlay reductions on stage smem

    // -------- merged single-sweep epilogue (always row AND col updates) ------
    float* rMin = (float*)dsm;            // [2][128]
    float* rMax = rMin + 256;
    float* cMin = rMax + 256;             // [4][64]
    float* cMax = cMin + 256;

    int   myTi[4];
    float mySa[4];
    #pragma unroll
    for (int mt = 0; mt < 2; mt++)
        #pragma unroll
        for (int h = 0; h < 2; h++) {
            int r = wr*32 + mt*16 + h*8 + g;
            myTi[mt*2+h] = sTi[r];
            mySa[mt*2+h] = sSa[r];
        }
    float rowMn[4] = {FBIG,FBIG,FBIG,FBIG};
    float rowMx[4] = {-FBIG,-FBIG,-FBIG,-FBIG};

    #pragma unroll
    for (int nt = 0; nt < 4; nt++) {
        #pragma unroll
        for (int e = 0; e < 2; e++) {
            int   cidx = wc*32 + nt*8 + t4*2 + e;
            int   tj   = sTj[cidx];
            float sb   = sSb[cidx];
            float cMn = FBIG, cMx = -FBIG;
            #pragma unroll
            for (int mt = 0; mt < 2; mt++) {
                #pragma unroll
                for (int h = 0; h < 2; h++) {
                    float v  = (float)acc[mt][nt][h*2 + e];
                    float vb = v * sb;
                    float va = v * mySa[mt*2+h];
                    if (myTi[mt*2+h] == tj) {
                        rowMn[mt*2+h] = fminf(rowMn[mt*2+h], vb);
                        cMn = fminf(cMn, va);
                    } else {
                        rowMx[mt*2+h] = fmaxf(rowMx[mt*2+h], vb);
                        cMx = fmaxf(cMx, va);
                    }
                }
            }
            cMn = fminf(cMn, __shfl_xor_sync(0xffffffffu, cMn, 4));
            cMn = fminf(cMn, __shfl_xor_sync(0xffffffffu, cMn, 8));
            cMn = fminf(cMn, __shfl_xor_sync(0xffffffffu, cMn, 16));
            cMx = fmaxf(cMx, __shfl_xor_sync(0xffffffffu, cMx, 4));
            cMx = fmaxf(cMx, __shfl_xor_sync(0xffffffffu, cMx, 8));
            cMx = fmaxf(cMx, __shfl_xor_sync(0xffffffffu, cMx, 16));
            if (g == 0) {
                cMin[wr*BN + cidx] = cMn * sb;
                cMax[wr*BN + cidx] = cMx * sb;
            }
        }
    }
    #pragma unroll
    for (int q = 0; q < 4; q++) {
        float mn = rowMn[q], mx = rowMx[q];
        mn = fminf(mn, __shfl_xor_sync(0xffffffffu, mn, 1));
        mn = fminf(mn, __shfl_xor_sync(0xffffffffu, mn, 2));
        mx = fmaxf(mx, __shfl_xor_sync(0xffffffffu, mx, 1));
        mx = fmaxf(mx, __shfl_xor_sync(0xffffffffu, mx, 2));
        if (t4 == 0) {
            int   mt = q >> 1, h = q & 1;
            int   r  = wr*32 + mt*16 + h*8 + g;
            float sa = mySa[q];
            rMin[wc*BM + r] = mn * sa;
            rMax[wc*BM + r] = mx * sa;
        }
    }
    __syncthreads();

    if (tid < BM) {                 // rows -> rowBase
        float mn = fminf(rMin[tid], rMin[BM + tid]);
        float mx = fmaxf(rMax[tid], rMax[BM + tid]);
        atomicMin(&g_minpos[rowBase + tid], ordu(mn));
        atomicMax(&g_maxneg[rowBase + tid], ordu(mx));
    } else if (tid < BM + BN) {     // cols -> colBase
        int cc = tid - BM;
        float mn = FBIG, mx = -FBIG;
        #pragma unroll
        for (int w = 0; w < 4; w++) {
            mn = fminf(mn, cMin[w*BN + cc]);
            mx = fmaxf(mx, cMax[w*BN + cc]);
        }
        atomicMin(&g_minpos[colBase + cc], ordu(mn));
        atomicMax(&g_maxneg[colBase + cc], ordu(mx));
    }

    // -------- fused final: last tile computes the loss --------
    __syncthreads();
    if (tid == 0) {
        __threadfence();
        sLast = (atomicAdd(&g_done, 1u) == NT2 - 1);
    }
    __syncthreads();
    if (sLast) {
        float s = 0.0f;
        #pragma unroll
        for (int i = 0; i < NROWS/256; i++) {
            int r = tid + i*256;
            float mx = deordu(__ldcg(&g_maxneg[r]));
            float mn = deordu(__ldcg(&g_minpos[r]));
            s += fmaxf(mx - mn + LMARGIN, 0.0f);
        }
        #pragma unroll
        for (int o = 16; o > 0; o >>= 1) s += __shfl_xor_sync(0xffffffffu, s, o);
        float* sm = (float*)dsm;
        if (lane == 0) sm[wid] = s;
        __syncthreads();
        if (tid == 0) {
            float tot = 0.0f;
            #pragma unroll
            for (int w = 0; w < 8; w++) tot += sm[w];
            out[0] = tot / (float)NROWS;
        }
    }
}

// ---------------- launch ------------------------------------------------------
extern "C" void kernel_launch(void* const* d_in, const int* in_sizes, int n_in,
                              void* d_out, int out_size)
{
    (void)in_sizes; (void)n_in; (void)out_size;
    const float* x   = (const float*)d_in[0];
    const int*   t32 = (const int*)d_in[1];

    cudaFuncSetAttribute(k_gemm_reduce,
                         cudaFuncAttributeMaxDynamicSharedMemorySize, SMEM_DYN);
    k_normalize<<<NROWS/16, 256>>>(x, t32);
    k_gemm_reduce<<<NT2, 256, SMEM_DYN>>>((float*)d_out);
}

// round 16
// speedup vs baseline: 1.0549x; 1.0549x over previous
#include <cuda_runtime.h>
#include <cstdint>

#define NROWS 8192
#define DDIM  512
#define BM    128
#define BK    64                       /* K (int8 elems) per stage */
#define NITER (DDIM/BK)                /* 8 */
#define NBLK  (NROWS/BM)               /* 64 */
#define NTRI  (NBLK*(NBLK+1)/2)        /* 2080 */
#define STRB  80                       /* smem row stride bytes */
#define TILEB (BM*STRB)                /* 10240 B per matrix per stage */
#define STAGES 3
#define SMEM_DYN (STAGES*2*TILEB)      /* 61440 B */
#define LMARGIN 0.5f
#define FBIG  3.402823466e+38f

// ---------------- scratch (static device globals; no allocation) -------------
__device__ int8_t   g_q8[NROWS*DDIM];     // quantized normalized rows (4 MB)
__device__ float    g_scl[NROWS];         // per-row dequant scale
__device__ unsigned g_minpos[NROWS];
__device__ unsigned g_maxneg[NROWS];
__device__ int      g_tgt[NROWS];

__device__ __forceinline__ unsigned ordu(float f) {
    unsigned u = __float_as_uint(f);
    return (u & 0x80000000u) ? ~u : (u | 0x80000000u);
}
__device__ __forceinline__ float deordu(unsigned u) {
    return (u & 0x80000000u) ? __uint_as_float(u & 0x7fffffffu)
                             : __uint_as_float(~u);
}
__device__ __forceinline__ uint32_t smem_u32(const void* p) {
    uint32_t a;
    asm("{ .reg .u64 t; cvta.to.shared.u64 t, %1; cvt.u32.u64 %0, t; }"
        : "=r"(a) : "l"(p));
    return a;
}
__device__ __forceinline__ void cpasync16(uint32_t dst, const void* src) {
    asm volatile("cp.async.cg.shared.global [%0], [%1], 16;"
                 :: "r"(dst), "l"(src) : "memory");
}
__device__ __forceinline__ void cpcommit() {
    asm volatile("cp.async.commit_group;" ::: "memory");
}
template <int N>
__device__ __forceinline__ void cpwait() {
    asm volatile("cp.async.wait_group %0;" :: "n"(N) : "memory");
}
__device__ __forceinline__ void ldsm4(unsigned* r, uint32_t addr) {
    asm volatile("ldmatrix.sync.aligned.m8n8.x4.shared.b16 {%0,%1,%2,%3}, [%4];"
                 : "=r"(r[0]), "=r"(r[1]), "=r"(r[2]), "=r"(r[3]) : "r"(addr));
}
__device__ __forceinline__ void mma_s8(int* c, const unsigned* a, const unsigned* b)
{
    asm volatile(
        "mma.sync.aligned.m16n8k32.row.col.s32.s8.s8.s32 "
        "{%0,%1,%2,%3},{%4,%5,%6,%7},{%8,%9},{%0,%1,%2,%3};"
        : "+r"(c[0]), "+r"(c[1]), "+r"(c[2]), "+r"(c[3])
        : "r"(a[0]), "r"(a[1]), "r"(a[2]), "r"(a[3]), "r"(b[0]), "r"(b[1]));
}

// -------- kernel 1: L2-normalize -> per-row int8 quant (1 row per warp) ------
__global__ void k_normalize(const float* __restrict__ x, const int* __restrict__ t32)
{
    int tid  = threadIdx.x;
    int wid  = tid >> 5;
    int lane = tid & 31;
    int row  = blockIdx.x * 8 + wid;

    const float4* xr = (const float4*)(x + (size_t)row * DDIM);
    float4 v[4];
    #pragma unroll
    for (int i = 0; i < 4; i++) v[i] = xr[lane + 32*i];
    float ss = 0.0f, ma = 0.0f;
    #pragma unroll
    for (int i = 0; i < 4; i++) {
        ss += v[i].x*v[i].x + v[i].y*v[i].y + v[i].z*v[i].z + v[i].w*v[i].w;
        ma  = fmaxf(ma, fmaxf(fmaxf(fabsf(v[i].x), fabsf(v[i].y)),
                              fmaxf(fabsf(v[i].z), fabsf(v[i].w))));
    }
    #pragma unroll
    for (int o = 16; o > 0; o >>= 1) {
        ss += __shfl_xor_sync(0xffffffffu, ss, o);
        ma  = fmaxf(ma, __shfl_xor_sync(0xffffffffu, ma, o));
    }
    float qs  = 127.0f / ma;               // raw -> int8
    float scl = ma * rsqrtf(ss) * (1.0f/127.0f);  // int8 -> normalized float

    // int64-vs-int32 target detection: int64 targets (<512) => odd words all 0
    int hv = t32[2*lane + 1];
    unsigned bal = __ballot_sync(0xffffffffu, hv == 0);
    bool is64 = (bal == 0xffffffffu);
    if (lane == 0) {
        g_minpos[row] = ordu(FBIG);
        g_maxneg[row] = ordu(-FBIG);
        g_tgt[row]    = is64 ? t32[2*row] : t32[row];
        g_scl[row]    = scl;
    }

    #pragma unroll
    for (int i = 0; i < 4; i++) {
        int q0 = __float2int_rn(v[i].x * qs);
        int q1 = __float2int_rn(v[i].y * qs);
        int q2 = __float2int_rn(v[i].z * qs);
        int q3 = __float2int_rn(v[i].w * qs);
        unsigned pk = (unsigned)(q0 & 0xff) | ((unsigned)(q1 & 0xff) << 8) |
                      ((unsigned)(q2 & 0xff) << 16) | ((unsigned)(q3 & 0xff) << 24);
        *(unsigned*)(g_q8 + (size_t)row * DDIM + (lane + 32*i)*4) = pk;
    }
}

// ---------------- kernel 2: fused symmetric int8 GEMM + masked min/max ------
// 128x128 triangular tiles, 256 threads = 8 warps (4 wr x 2 wc), 32x64/warp.
// 3-stage cp.async pipeline; ldmatrix.x4 frags (stride-80B, conflict-free);
// m16n8k32 s8 IMMA, s32 acc; dequant in epilogue via per-row scales.
// (This exact configuration benched 93.06 us; R9-R13 perturbations all >= it.)
__global__ void __launch_bounds__(256, 2) k_gemm_reduce()
{
    extern __shared__ __align__(16) char dsm[];

    // triangular block index -> (bi, bj), bj >= bi
    int b = blockIdx.x;
    int bi = 0, rem = b;
    while (rem >= NBLK - bi) { rem -= NBLK - bi; bi++; }
    int bj = bi + rem;

    __shared__ int   sTi[BM], sTj[BM];
    __shared__ float sSa[BM], sSb[BM];

    int tid  = threadIdx.x;
    int wid  = tid >> 5;
    int lane = tid & 31;
    int wr   = wid >> 1;          // 0..3 : rows wr*32..+31
    int wc   = wid & 1;           // 0..1 : cols wc*64..+63
    int g    = lane >> 2;         // 0..7
    int t4   = lane & 3;          // 0..3

    if (tid < BM) { sTi[tid] = g_tgt[bi*BM + tid]; sSa[tid] = g_scl[bi*BM + tid]; }
    else { int c2 = tid - BM; sTj[c2] = g_tgt[bj*BM + c2]; sSb[c2] = g_scl[bj*BM + c2]; }

    const int8_t* gA = g_q8 + (size_t)(bi*BM) * DDIM;
    const int8_t* gB = g_q8 + (size_t)(bj*BM) * DDIM;
    uint32_t dsmBase = smem_u32(dsm);

    // cp.async: 2 x 16B per thread per matrix per stage (512 chunks/matrix)
    int ldRow[2], ldSeg[2];
    #pragma unroll
    for (int i = 0; i < 2; i++) {
        int idx = i*256 + tid;
        ldRow[i] = idx >> 2;
        ldSeg[i] = idx & 3;
    }
    auto issue_stage = [&](int c) {
        int k0 = c * BK;
        uint32_t dA = dsmBase + (unsigned)(c % STAGES) * (2*TILEB);
        uint32_t dB = dA + TILEB;
        #pragma unroll
        for (int i = 0; i < 2; i++) {
            unsigned off = ldRow[i]*STRB + ldSeg[i]*16;
            cpasync16(dA + off, gA + (size_t)ldRow[i]*DDIM + k0 + ldSeg[i]*16);
            cpasync16(dB + off, gB + (size_t)ldRow[i]*DDIM + k0 + ldSeg[i]*16);
        }
        cpcommit();
    };

    // ldmatrix per-lane byte offsets
    unsigned aoff[2], boff[4];
    {
        int rsel = lane & 15;
        int kby  = ((lane >> 4) & 1) * 16;
        #pragma unroll
        for (int mt = 0; mt < 2; mt++)
            aoff[mt] = (wr*32 + mt*16 + rsel)*STRB + kby;
        #pragma unroll
        for (int np = 0; np < 4; np++)
            boff[np] = (wc*64 + np*16 + rsel)*STRB + kby;
    }

    int acc[2][8][4];
    #pragma unroll
    for (int mt = 0; mt < 2; mt++)
        #pragma unroll
        for (int nt = 0; nt < 8; nt++)
            #pragma unroll
            for (int e = 0; e < 4; e++) acc[mt][nt][e] = 0;

    issue_stage(0);
    issue_stage(1);

    for (int c = 0; c < NITER; c++) {
        cpwait<1>();                 // stage c resident
        __syncthreads();             // fences iter c-1 reads of buf (c-1)%3
        if (c + 2 < NITER) issue_stage(c + 2);
        else cpcommit();             // keep group count in step

        uint32_t bA = dsmBase + (unsigned)(c % STAGES) * (2*TILEB);
        uint32_t bB = bA + TILEB;
        #pragma unroll
        for (int ks = 0; ks < 2; ks++) {
            unsigned kk = ks*32;     // 32 int8 = 32 B per k32 step
            unsigned afr[2][4], btmp[4][4];
            #pragma unroll
            for (int mt = 0; mt < 2; mt++) ldsm4(afr[mt], bA + aoff[mt] + kk);
            #pragma unroll
            for (int np = 0; np < 4; np++) ldsm4(btmp[np], bB + boff[np] + kk);
            #pragma unroll
            for (int mt = 0; mt < 2; mt++) {
                #pragma unroll
                for (int np = 0; np < 4; np++) {
                    unsigned b0[2] = { btmp[np][0], btmp[np][2] };
                    unsigned b1[2] = { btmp[np][1], btmp[np][3] };
                    mma_s8(acc[mt][2*np],   afr[mt], b0);
                    mma_s8(acc[mt][2*np+1], afr[mt], b1);
                }
            }
        }
    }
    __syncthreads();   // compute done; overlay reductions on stage smem

    // -------- epilogue: dequant + masked min/max --------
    float* rMin = (float*)dsm;            // [2][128]
    float* rMax = rMin + 256;
    float* cMin = rMax + 256;             // [4][128]
    float* cMax = cMin + 512;
    bool offd = (bi != bj);

    // row pass: reduce over t4 via shuffles 1,2
    #pragma unroll
    for (int mt = 0; mt < 2; mt++) {
        #pragma unroll
        for (int h = 0; h < 2; h++) {
            int   r  = wr*32 + mt*16 + h*8 + g;
            int   ti = sTi[r];
            float sa = sSa[r];
            float mn = FBIG, mx = -FBIG;
            #pragma unroll
            for (int nt = 0; nt < 8; nt++) {
                #pragma unroll
                for (int e = 0; e < 2; e++) {
                    int   cidx = wc*64 + nt*8 + t4*2 + e;
                    float v = (float)acc[mt][nt][h*2 + e] * sa * sSb[cidx];
                    if (ti == sTj[cidx]) mn = fminf(mn, v);
                    else                 mx = fmaxf(mx, v);
                }
            }
            mn = fminf(mn, __shfl_xor_sync(0xffffffffu, mn, 1));
            mn = fminf(mn, __shfl_xor_sync(0xffffffffu, mn, 2));
            mx = fmaxf(mx, __shfl_xor_sync(0xffffffffu, mx, 1));
            mx = fmaxf(mx, __shfl_xor_sync(0xffffffffu, mx, 2));
            if (t4 == 0) { rMin[wc*BM + r] = mn; rMax[wc*BM + r] = mx; }
        }
    }
    // col pass: reduce over g via shuffles 4,8,16 (off-diagonal only)
    if (offd) {
        #pragma unroll
        for (int nt = 0; nt < 8; nt++) {
            #pragma unroll
            for (int e = 0; e < 2; e++) {
                int   cidx = wc*64 + nt*8 + t4*2 + e;
                int   tj   = sTj[cidx];
                float sb   = sSb[cidx];
                float mn = FBIG, mx = -FBIG;
                #pragma unroll
                for (int mt = 0; mt < 2; mt++) {
                    #pragma unroll
                    for (int h = 0; h < 2; h++) {
                        int   r = wr*32 + mt*16 + h*8 + g;
                        float v = (float)acc[mt][nt][h*2 + e] * sSa[r] * sb;
                        if (sTi[r] == tj) mn = fminf(mn, v);
                        else              mx = fmaxf(mx, v);
                    }
                }
                mn = fminf(mn, __shfl_xor_sync(0xffffffffu, mn, 4));
                mn = fminf(mn, __shfl_xor_sync(0xffffffffu, mn, 8));
                mn = fminf(mn, __shfl_xor_sync(0xffffffffu, mn, 16));
                mx = fmaxf(mx, __shfl_xor_sync(0xffffffffu, mx, 4));
                mx = fmaxf(mx, __shfl_xor_sync(0xffffffffu, mx, 8));
                mx = fmaxf(mx, __shfl_xor_sync(0xffffffffu, mx, 16));
                if (g == 0) { cMin[wr*BM + cidx] = mn; cMax[wr*BM + cidx] = mx; }
            }
        }
    }
    __syncthreads();

    if (tid < BM) {          // row results -> bi rows
        float mn = fminf(rMin[tid], rMin[BM + tid]);
        float mx = fmaxf(rMax[tid], rMax[BM + tid]);
        atomicMin(&g_minpos[bi*BM + tid], ordu(mn));
        atomicMax(&g_maxneg[bi*BM + tid], ordu(mx));
    } else if (offd) {       // col results -> bj rows
        int cc = tid - BM;
        float mn = FBIG, mx = -FBIG;
        #pragma unroll
        for (int w = 0; w < 4; w++) {
            mn = fminf(mn, cMin[w*BM + cc]);
            mx = fmaxf(mx, cMax[w*BM + cc]);
        }
        atomicMin(&g_minpos[bj*BM + cc], ordu(mn));
        atomicMax(&g_maxneg[bj*BM + cc], ordu(mx));
    }
}

// ---------------- kernel 3: loss = mean(relu(maxneg - minpos + margin)) ------
__global__ void k_final(float* __restrict__ out)
{
    int tid = threadIdx.x;
    float s = 0.0f;
    #pragma unroll
    for (int i = 0; i < NROWS/1024; i++) {
        int r = tid + i*1024;
        float mx = deordu(g_maxneg[r]);
        float mn = deordu(g_minpos[r]);
        s += fmaxf(mx - mn + LMARGIN, 0.0f);
    }
    __shared__ float sm[1024];
    sm[tid] = s;
    __syncthreads();
    #pragma unroll
    for (int o = 512; o > 0; o >>= 1) {
        if (tid < o) sm[tid] += sm[tid + o];
        __syncthreads();
    }
    if (tid == 0) out[0] = sm[0] / (float)NROWS;
}

// ---------------- launch ------------------------------------------------------
extern "C" void kernel_launch(void* const* d_in, const int* in_sizes, int n_in,
                              void* d_out, int out_size)
{
    (void)in_sizes; (void)n_in; (void)out_size;
    const float* x   = (const float*)d_in[0];
    const int*   t32 = (const int*)d_in[1];

    cudaFuncSetAttribute(k_gemm_reduce,
                         cudaFuncAttributeMaxDynamicSharedMemorySize, SMEM_DYN);
    k_normalize<<<NROWS/8, 256>>>(x, t32);
    k_gemm_reduce<<<NTRI, 256, SMEM_DYN>>>();
    k_final<<<1, 1024>>>((float*)d_out);
}